// round 9
// baseline (speedup 1.0000x reference)
#include <cuda_runtime.h>
#include <cuda_fp16.h>
#include <math_constants.h>
#include <cstdint>

#define N_TOKENS   16384
#define DIM        2048
#define NEXP       64
#define NCOLS      128
#define TOK_BLK    128
#define NBLOCKS    (N_TOKENS / TOK_BLK)   // 128
#define NTHREADS   512
#define KC         64
#define NCHUNK     (DIM / KC)             // 32
#define EPS        1e-9f
#define FIX_THR    4e-3f                  // ~14 sigma of fp16 1-pass logit error

#define PADB       144
#define TILE_BYTES (128 * PADB)           // 18432
#define A_HI       0
#define B_HI       TILE_BYTES
#define ST_SIZE    (2 * TILE_BYTES)       // 36864
#define B_CHUNK_U16X (TILE_BYTES / 16)    // 1152
#define SMEM_BYTES (1024 + 2 * ST_SIZE)   // 74752; epilogue needs exactly 2*ST_SIZE

// ---- static device scratch ----
__device__ uint4 g_wpack[NCHUNK * B_CHUNK_U16X];   // 576KB fp16 W
__device__ float g_imp_part [NBLOCKS * NEXP];
__device__ float g_load_part[NBLOCKS * NEXP];
__device__ unsigned char g_flag[N_TOKENS];

// ======================= helpers =======================
__device__ __forceinline__ uint32_t smem_u32(const void* p) {
    uint32_t a;
    asm("{ .reg .u64 t; cvta.to.shared.u64 t, %1; cvt.u32.u64 %0, t; }" : "=r"(a) : "l"(p));
    return a;
}
__device__ __forceinline__ void ldsm_x4(uint32_t (&r)[4], uint32_t addr) {
    asm volatile("ldmatrix.sync.aligned.m8n8.x4.shared.b16 {%0,%1,%2,%3}, [%4];"
                 : "=r"(r[0]), "=r"(r[1]), "=r"(r[2]), "=r"(r[3]) : "r"(addr));
}
__device__ __forceinline__ void mma16816h(float* d, const uint32_t* a, uint32_t b0, uint32_t b1) {
    asm volatile("mma.sync.aligned.m16n8k16.row.col.f32.f16.f16.f32 "
                 "{%0,%1,%2,%3}, {%4,%5,%6,%7}, {%8,%9}, {%0,%1,%2,%3};"
                 : "+f"(d[0]), "+f"(d[1]), "+f"(d[2]), "+f"(d[3])
                 : "r"(a[0]), "r"(a[1]), "r"(a[2]), "r"(a[3]), "r"(b0), "r"(b1));
}
#define CP_ASYNC16(dst, src) \
    asm volatile("cp.async.cg.shared.global [%0], [%1], 16;" :: "r"(dst), "l"(src))
#define CP_COMMIT()  asm volatile("cp.async.commit_group;")
#define CP_WAIT0()   asm volatile("cp.async.wait_group 0;")

__device__ __forceinline__ uint4 cvt8h(float4 a, float4 b) {
    __half2 h0 = __floats2half2_rn(a.x, a.y);
    __half2 h1 = __floats2half2_rn(a.z, a.w);
    __half2 h2 = __floats2half2_rn(b.x, b.y);
    __half2 h3 = __floats2half2_rn(b.z, b.w);
    uint4 r;
    r.x = *reinterpret_cast<uint32_t*>(&h0);
    r.y = *reinterpret_cast<uint32_t*>(&h1);
    r.z = *reinterpret_cast<uint32_t*>(&h2);
    r.w = *reinterpret_cast<uint32_t*>(&h3);
    return r;
}

// ======================= W precompute =======================
__global__ void __launch_bounds__(256) wpack_kernel(const float* __restrict__ Wg,
                                                    const float* __restrict__ Wn) {
    int id = blockIdx.x * 256 + threadIdx.x;
    int chunk = id >> 10;
    int rem   = id & 1023;
    int col = rem >> 3, u = rem & 7;
    const float* src = (col < NEXP ? Wg + (size_t)col * DIM : Wn + (size_t)(col - NEXP) * DIM)
                       + chunk * KC + u * 8;
    float4 a = ((const float4*)src)[0];
    float4 b = ((const float4*)src)[1];
    char* base = (char*)g_wpack + (size_t)chunk * TILE_BYTES;
    *(uint4*)(base + col * PADB + u * 16) = cvt8h(a, b);
}

// ======================= main: fp16 1-pass GEMM + approx epilogue =======================
__global__ void __launch_bounds__(NTHREADS)
router_main_kernel(const float* __restrict__ x,
                   const float* __restrict__ noise,
                   float* __restrict__ out)
{
    extern __shared__ char sm[];
    const uint32_t smb = smem_u32(sm);
    const uint32_t stb = (smb + 1023u) & ~1023u;
    char* st_ptr = sm + (stb - smb);

    const int tid  = threadIdx.x;
    const int wid  = tid >> 5;           // 0..15
    const int lane = tid & 31;
    const int wm   = wid >> 1;           // 0..7
    const int wn   = wid & 1;            // 0..1
    const int tok0 = blockIdx.x * TOK_BLK;

    const int arow = tid >> 3, au = tid & 7;

    float acc[8][4];
#pragma unroll
    for (int j = 0; j < 8; ++j)
#pragma unroll
        for (int q = 0; q < 4; ++q) acc[j][q] = 0.f;

    // ---- prologue ----
    {
        const uint4* src = g_wpack;
        uint32_t d = stb + B_HI;
#pragma unroll
        for (int t = 0; t < 3; ++t) {
            int idx = tid + t * 512;
            if (idx < B_CHUNK_U16X) CP_ASYNC16(d + idx * 16, src + idx);
        }
        CP_COMMIT();

        float4 ar[4];
#pragma unroll
        for (int t = 0; t < 2; ++t) {
            const float4* p = (const float4*)(x + (size_t)(tok0 + arow + t * 64) * DIM + au * 8);
            ar[2*t]   = p[0];
            ar[2*t+1] = p[1];
        }
#pragma unroll
        for (int t = 0; t < 2; ++t) {
            int r = arow + t * 64;
            *(uint4*)(st_ptr + A_HI + r * PADB + au * 16) = cvt8h(ar[2*t], ar[2*t+1]);
        }
        CP_WAIT0();
        __syncthreads();
    }

    const uint32_t a_lane = (uint32_t)((wm * 16 + (lane & 15)) * PADB + (lane >> 4) * 16);
    const uint32_t b_lane = (uint32_t)((wn * 64 + (lane & 15)) * PADB + (lane >> 4) * 16);

    for (int c = 0; c < NCHUNK; ++c) {
        const int buf = c & 1;
        const uint32_t sb = stb + buf * ST_SIZE;
        const bool pf = (c + 1 < NCHUNK);
        char* stn = st_ptr + (buf ^ 1) * ST_SIZE;

        float4 ar[4];
        if (pf) {
            const uint4* src = g_wpack + (size_t)(c + 1) * B_CHUNK_U16X;
            uint32_t d = stb + (buf ^ 1) * ST_SIZE + B_HI;
#pragma unroll
            for (int t = 0; t < 3; ++t) {
                int idx = tid + t * 512;
                if (idx < B_CHUNK_U16X) CP_ASYNC16(d + idx * 16, src + idx);
            }
            CP_COMMIT();
            const int koff = (c + 1) * KC;
#pragma unroll
            for (int t = 0; t < 2; ++t) {
                const float4* p = (const float4*)(x + (size_t)(tok0 + arow + t * 64) * DIM + koff + au * 8);
                ar[2*t]   = p[0];
                ar[2*t+1] = p[1];
            }
        }

#pragma unroll
        for (int ks = 0; ks < 4; ++ks) {
            const uint32_t ko = ks * 32;
            uint32_t ah[4];
            ldsm_x4(ah, sb + A_HI + a_lane + ko);
            uint32_t bh[4][4];
#pragma unroll
            for (int p = 0; p < 4; ++p)
                ldsm_x4(bh[p], sb + B_HI + b_lane + p * 16 * PADB + ko);
#pragma unroll
            for (int p = 0; p < 4; ++p)
#pragma unroll
                for (int h = 0; h < 2; ++h)
                    mma16816h(acc[2 * p + h], ah, bh[p][h], bh[p][2 + h]);
        }

        if (pf) {
#pragma unroll
            for (int t = 0; t < 2; ++t) {
                int r = arow + t * 64;
                *(uint4*)(stn + A_HI + r * PADB + au * 16) = cvt8h(ar[2*t], ar[2*t+1]);
            }
            CP_WAIT0();
        }
        __syncthreads();
    }

    // ---------------- epilogue (overlay) ----------------
    float* smf = (float*)st_ptr;
    const int LSTR = 129;
    const int LOGI = 0;                       // [128][129]: 0-63 gate logits, 64-127 noise->sd
    const int V2O  = 128 * 129;
    const int V3O  = V2O + 128, W1O = V3O + 128, W2O = W1O + 128;
    const int I1O  = W2O + 128, I2O = I1O + 128;
    const int IMPO = I2O + 128, LDO = IMPO + 512;   // [8][64] each
    const int FLGO = LDO + 512;                     // [128] ints

#pragma unroll
    for (int nt = 0; nt < 8; ++nt)
#pragma unroll
        for (int ci = 0; ci < 4; ++ci) {
            int row = wm * 16 + (lane >> 2) + (ci >> 1) * 8;
            int col = wn * 64 + nt * 8 + (lane & 3) * 2 + (ci & 1);
            smf[LOGI + row * LSTR + col] = acc[nt][ci];
        }
    __syncthreads();

    // E1: one thread per token — approx decision + flag near-ties
    if (tid < TOK_BLK) {
        const int t = tid;
        const float* nrow = noise + (size_t)(tok0 + t) * NEXP;
        float v1 = -CUDART_INF_F, v2 = -CUDART_INF_F, v3 = -CUDART_INF_F;
        int i1 = 0, i2 = 0;
#pragma unroll 4
        for (int e = 0; e < NEXP; ++e) {
            float lg = smf[LOGI + t * LSTR + e];
            float nl = smf[LOGI + t * LSTR + NEXP + e];
            float sp = fmaxf(nl, 0.f) + log1pf(expf(-fabsf(nl)));
            float sd = sp + EPS;
            smf[LOGI + t * LSTR + NEXP + e] = sd;     // overwrite with noise_std
            float nz = fmaf(nrow[e], sd, lg);
            if (nz > v1)      { v3 = v2; v2 = v1; i2 = i1; v1 = nz; i1 = e; }
            else if (nz > v2) { v3 = v2; v2 = nz; i2 = e; }
            else if (nz > v3) { v3 = nz; }
        }
        float ed  = expf(v2 - v1);
        float inv = 1.f / (1.f + ed);
        float w1 = inv, w2 = ed * inv;

        const int tg = tok0 + t;
        int flag = ((v1 - v2) < FIX_THR) || ((v2 - v3) < FIX_THR);
        out[2 * tg]                    = (float)i1;
        out[2 * tg + 1]                = (float)i2;
        out[2 * N_TOKENS + 2 * tg]     = w1;
        out[2 * N_TOKENS + 2 * tg + 1] = w2;
        out[4 * N_TOKENS + tg]         = w1;
        g_flag[tg] = (unsigned char)flag;
        ((int*)(smf + FLGO))[t] = flag;
        smf[V2O + t] = v2; smf[V3O + t] = v3;
        smf[W1O + t] = w1; smf[W2O + t] = w2;
        ((int*)(smf + I1O))[t] = i1; ((int*)(smf + I2O))[t] = i2;
    }
    __syncthreads();

    // E2: partials, skipping flagged (fixup adds exact contributions)
    {
        const int e = tid & 63, g = tid >> 6;
        float imp = 0.f, ld = 0.f;
#pragma unroll 4
        for (int t = g * 16; t < g * 16 + 16; ++t) {
            if (((int*)(smf + FLGO))[t]) continue;
            int ii1 = ((int*)(smf + I1O))[t], ii2 = ((int*)(smf + I2O))[t];
            bool in1 = (ii1 == e), in2 = (ii2 == e);
            if (in1) imp += smf[W1O + t];
            if (in2) imp += smf[W2O + t];
            float kth = (in1 || in2) ? smf[V3O + t] : smf[V2O + t];
            float sd  = smf[LOGI + t * LSTR + NEXP + e];
            float lg  = smf[LOGI + t * LSTR + e];
            float z   = (lg - kth) / (sd + EPS);
            ld += 0.5f * (1.f + erff(z * 0.70710678118654752f));
        }
        smf[IMPO + g * 64 + e] = imp;
        smf[LDO  + g * 64 + e] = ld;
    }
    __syncthreads();

    if (tid < NEXP) {
        float si = 0.f, sl = 0.f;
#pragma unroll
        for (int g = 0; g < 8; ++g) { si += smf[IMPO + g * 64 + tid]; sl += smf[LDO + g * 64 + tid]; }
        g_imp_part [blockIdx.x * NEXP + tid] = si;
        g_load_part[blockIdx.x * NEXP + tid] = sl;
    }
}

// ======================= fixup: exact compensated recompute of flagged tokens =======================
__global__ void __launch_bounds__(1024)
router_fixup_kernel(const float* __restrict__ x, const float* __restrict__ noise,
                    const float* __restrict__ Wg, const float* __restrict__ Wn,
                    float* __restrict__ out)
{
    __shared__ float xs[DIM];
    __shared__ float lgf[NCOLS];
    __shared__ float sds[NEXP], nzs[NEXP];
    __shared__ float seg_s[1024], seg_c[1024];
    __shared__ float sv2, sv3, sw1, sw2;
    __shared__ int   si1, si2;
    const int tid = threadIdx.x;
    const int base = blockIdx.x * TOK_BLK;

    float imp_acc = 0.f, ld_acc = 0.f;      // valid for tid<64 (expert id)

    for (int t = base; t < base + TOK_BLK; ++t) {
        if (!g_flag[t]) continue;

        if (tid < DIM / 4)
            ((float4*)xs)[tid] = ((const float4*)(x + (size_t)t * DIM))[tid];
        __syncthreads();

        // compensated dot: col = tid>>3 (0..127), seg = tid&7 (256 elems each)
        const int col = tid >> 3, seg = tid & 7;
        const float* w = (col < NEXP ? Wg + (size_t)col * DIM : Wn + (size_t)(col - NEXP) * DIM);
        float s = 0.f, c = 0.f;
        const int k0 = seg * 256;
        for (int k = k0; k < k0 + 256; ++k) {
            float xv = xs[k], wv = w[k];
            float p  = xv * wv;
            float e  = fmaf(xv, wv, -p);       // TwoProd error
            float t0 = s + p;                  // Neumaier TwoSum
            c += (fabsf(s) >= fabsf(p)) ? ((s - t0) + p) : ((p - t0) + s);
            s = t0;
            c += e;
        }
        seg_s[tid] = s; seg_c[tid] = c;
        __syncthreads();

        if (tid < NCOLS) {
            double v = 0.0;
#pragma unroll
            for (int q = 0; q < 8; ++q)
                v += (double)seg_s[tid * 8 + q] + (double)seg_c[tid * 8 + q];
            lgf[tid] = (float)v;               // round to fp32 granularity
        }
        __syncthreads();

        if (tid < NEXP) {
            float nl = lgf[NEXP + tid];
            float sp = fmaxf(nl, 0.f) + log1pf(expf(-fabsf(nl)));
            sds[tid] = sp + EPS;
            nzs[tid] = fmaf(noise[(size_t)t * NEXP + tid], sds[tid], lgf[tid]);
        }
        __syncthreads();

        if (tid == 0) {
            float v1 = -CUDART_INF_F, v2 = -CUDART_INF_F, v3 = -CUDART_INF_F;
            int i1 = 0, i2 = 0;
            for (int e = 0; e < NEXP; ++e) {
                float nz = nzs[e];
                if (nz > v1)      { v3 = v2; v2 = v1; i2 = i1; v1 = nz; i1 = e; }
                else if (nz > v2) { v3 = v2; v2 = nz; i2 = e; }
                else if (nz > v3) { v3 = nz; }
            }
            float ed  = expf(v2 - v1);
            float inv = 1.f / (1.f + ed);
            float w1 = inv, w2 = ed * inv;
            out[2 * t]                    = (float)i1;
            out[2 * t + 1]                = (float)i2;
            out[2 * N_TOKENS + 2 * t]     = w1;
            out[2 * N_TOKENS + 2 * t + 1] = w2;
            out[4 * N_TOKENS + t]         = w1;
            sv2 = v2; sv3 = v3; sw1 = w1; sw2 = w2; si1 = i1; si2 = i2;
        }
        __syncthreads();

        if (tid < NEXP) {
            bool in1 = (si1 == tid), in2 = (si2 == tid);
            if (in1) imp_acc += sw1;
            if (in2) imp_acc += sw2;
            float kth = (in1 || in2) ? sv3 : sv2;
            float z = (lgf[tid] - kth) / (sds[tid] + EPS);
            ld_acc += 0.5f * (1.f + erff(z * 0.70710678118654752f));
        }
        __syncthreads();
    }

    if (tid < NEXP) {
        g_imp_part [blockIdx.x * NEXP + tid] += imp_acc;
        g_load_part[blockIdx.x * NEXP + tid] += ld_acc;
    }
}

// ======================= finalize =======================
__global__ void __launch_bounds__(512) router_finalize_kernel(float* __restrict__ out)
{
    __shared__ float pimp[8][64], pld[8][64];
    const int tid = threadIdx.x;
    const int e = tid & 63, g = tid >> 6;
    float si = 0.f, sl = 0.f;
#pragma unroll
    for (int b = g; b < NBLOCKS; b += 8) {
        si += g_imp_part [b * NEXP + e];
        sl += g_load_part[b * NEXP + e];
    }
    pimp[g][e] = si; pld[g][e] = sl;
    __syncthreads();
    if (tid < 64) {
        float a = 0.f, b = 0.f;
#pragma unroll
        for (int q = 0; q < 8; ++q) { a += pimp[q][tid]; b += pld[q][tid]; }
        pimp[0][tid] = a; pld[0][tid] = b;
    }
    __syncthreads();
    if (tid == 0) {
        float mi = 0.f, ml = 0.f;
        for (int q = 0; q < NEXP; ++q) { mi += pimp[0][q]; ml += pld[0][q]; }
        mi *= (1.f / NEXP); ml *= (1.f / NEXP);
        float vi = 0.f, vl = 0.f;
        for (int q = 0; q < NEXP; ++q) {
            float di = pimp[0][q] - mi, dl = pld[0][q] - ml;
            vi += di * di; vl += dl * dl;
        }
        vi *= (1.f / NEXP); vl *= (1.f / NEXP);
        out[5 * N_TOKENS] = 0.1f * (vi / (mi * mi + EPS)) + 0.1f * (vl / (ml * ml + EPS));
    }
}

extern "C" void kernel_launch(void* const* d_in, const int* in_sizes, int n_in,
                              void* d_out, int out_size)
{
    const float* x     = (const float*)d_in[0];
    const float* noise = (const float*)d_in[1];
    const float* Wg    = (const float*)d_in[2];
    const float* Wn    = (const float*)d_in[3];
    float* out = (float*)d_out;

    cudaFuncSetAttribute(router_main_kernel,
                         cudaFuncAttributeMaxDynamicSharedMemorySize, SMEM_BYTES);
    wpack_kernel<<<128, 256>>>(Wg, Wn);
    router_main_kernel<<<NBLOCKS, NTHREADS, SMEM_BYTES>>>(x, noise, out);
    router_fixup_kernel<<<NBLOCKS, 1024>>>(x, noise, Wg, Wn, out);
    router_finalize_kernel<<<1, 512>>>(out);
}

// round 10
// speedup vs baseline: 16.0616x; 16.0616x over previous
#include <cuda_runtime.h>
#include <cuda_fp16.h>
#include <math_constants.h>
#include <cstdint>

#define N_TOKENS   16384
#define DIM        2048
#define NEXP       64
#define NCOLS      128
#define TOK_BLK    128
#define NBLOCKS    (N_TOKENS / TOK_BLK)   // 128
#define NTHREADS   512
#define KC         64
#define NCHUNK     (DIM / KC)             // 32
#define EPS        1e-9f
#define FIX_THR    4e-3f
#define WINDOW     8e-3f

#define PADB       144
#define TILE_BYTES (128 * PADB)           // 18432
#define A_HI       0
#define B_HI       TILE_BYTES
#define ST_SIZE    (2 * TILE_BYTES)       // 36864
#define B_CHUNK_U16X (TILE_BYTES / 16)    // 1152
#define SMEM_BYTES (1024 + 2 * ST_SIZE)

// ---- static device scratch ----
__device__ uint4 g_wpack[NCHUNK * B_CHUNK_U16X];   // 576KB fp16 W
__device__ float g_imp_part [NBLOCKS * NEXP];
__device__ float g_load_part[NBLOCKS * NEXP];
__device__ unsigned char g_flag[N_TOKENS];
__device__ float g_lgap[N_TOKENS * NEXP];          // approx gate logits (flagged only)
__device__ float g_sdap[N_TOKENS * NEXP];          // approx noise_std   (flagged only)

// ======================= helpers =======================
__device__ __forceinline__ uint32_t smem_u32(const void* p) {
    uint32_t a;
    asm("{ .reg .u64 t; cvta.to.shared.u64 t, %1; cvt.u32.u64 %0, t; }" : "=r"(a) : "l"(p));
    return a;
}
__device__ __forceinline__ void ldsm_x4(uint32_t (&r)[4], uint32_t addr) {
    asm volatile("ldmatrix.sync.aligned.m8n8.x4.shared.b16 {%0,%1,%2,%3}, [%4];"
                 : "=r"(r[0]), "=r"(r[1]), "=r"(r[2]), "=r"(r[3]) : "r"(addr));
}
__device__ __forceinline__ void mma16816h(float* d, const uint32_t* a, uint32_t b0, uint32_t b1) {
    asm volatile("mma.sync.aligned.m16n8k16.row.col.f32.f16.f16.f32 "
                 "{%0,%1,%2,%3}, {%4,%5,%6,%7}, {%8,%9}, {%0,%1,%2,%3};"
                 : "+f"(d[0]), "+f"(d[1]), "+f"(d[2]), "+f"(d[3])
                 : "r"(a[0]), "r"(a[1]), "r"(a[2]), "r"(a[3]), "r"(b0), "r"(b1));
}
#define CP_ASYNC16(dst, src) \
    asm volatile("cp.async.cg.shared.global [%0], [%1], 16;" :: "r"(dst), "l"(src))
#define CP_COMMIT()  asm volatile("cp.async.commit_group;")
#define CP_WAIT0()   asm volatile("cp.async.wait_group 0;")

__device__ __forceinline__ uint4 cvt8h(float4 a, float4 b) {
    __half2 h0 = __floats2half2_rn(a.x, a.y);
    __half2 h1 = __floats2half2_rn(a.z, a.w);
    __half2 h2 = __floats2half2_rn(b.x, b.y);
    __half2 h3 = __floats2half2_rn(b.z, b.w);
    uint4 r;
    r.x = *reinterpret_cast<uint32_t*>(&h0);
    r.y = *reinterpret_cast<uint32_t*>(&h1);
    r.z = *reinterpret_cast<uint32_t*>(&h2);
    r.w = *reinterpret_cast<uint32_t*>(&h3);
    return r;
}

// ======================= W precompute =======================
__global__ void __launch_bounds__(256) wpack_kernel(const float* __restrict__ Wg,
                                                    const float* __restrict__ Wn) {
    int id = blockIdx.x * 256 + threadIdx.x;
    int chunk = id >> 10;
    int rem   = id & 1023;
    int col = rem >> 3, u = rem & 7;
    const float* src = (col < NEXP ? Wg + (size_t)col * DIM : Wn + (size_t)(col - NEXP) * DIM)
                       + chunk * KC + u * 8;
    float4 a = ((const float4*)src)[0];
    float4 b = ((const float4*)src)[1];
    char* base = (char*)g_wpack + (size_t)chunk * TILE_BYTES;
    *(uint4*)(base + col * PADB + u * 16) = cvt8h(a, b);
}

// ======================= main: fp16 1-pass GEMM + approx epilogue =======================
__global__ void __launch_bounds__(NTHREADS)
router_main_kernel(const float* __restrict__ x,
                   const float* __restrict__ noise,
                   float* __restrict__ out)
{
    extern __shared__ char sm[];
    const uint32_t smb = smem_u32(sm);
    const uint32_t stb = (smb + 1023u) & ~1023u;
    char* st_ptr = sm + (stb - smb);

    const int tid  = threadIdx.x;
    const int wid  = tid >> 5;
    const int lane = tid & 31;
    const int wm   = wid >> 1;
    const int wn   = wid & 1;
    const int tok0 = blockIdx.x * TOK_BLK;

    const int arow = tid >> 3, au = tid & 7;

    float acc[8][4];
#pragma unroll
    for (int j = 0; j < 8; ++j)
#pragma unroll
        for (int q = 0; q < 4; ++q) acc[j][q] = 0.f;

    // ---- prologue ----
    {
        const uint4* src = g_wpack;
        uint32_t d = stb + B_HI;
#pragma unroll
        for (int t = 0; t < 3; ++t) {
            int idx = tid + t * 512;
            if (idx < B_CHUNK_U16X) CP_ASYNC16(d + idx * 16, src + idx);
        }
        CP_COMMIT();

        float4 ar[4];
#pragma unroll
        for (int t = 0; t < 2; ++t) {
            const float4* p = (const float4*)(x + (size_t)(tok0 + arow + t * 64) * DIM + au * 8);
            ar[2*t]   = p[0];
            ar[2*t+1] = p[1];
        }
#pragma unroll
        for (int t = 0; t < 2; ++t) {
            int r = arow + t * 64;
            *(uint4*)(st_ptr + A_HI + r * PADB + au * 16) = cvt8h(ar[2*t], ar[2*t+1]);
        }
        CP_WAIT0();
        __syncthreads();
    }

    const uint32_t a_lane = (uint32_t)((wm * 16 + (lane & 15)) * PADB + (lane >> 4) * 16);
    const uint32_t b_lane = (uint32_t)((wn * 64 + (lane & 15)) * PADB + (lane >> 4) * 16);

    for (int c = 0; c < NCHUNK; ++c) {
        const int buf = c & 1;
        const uint32_t sb = stb + buf * ST_SIZE;
        const bool pf = (c + 1 < NCHUNK);
        char* stn = st_ptr + (buf ^ 1) * ST_SIZE;

        float4 ar[4];
        if (pf) {
            const uint4* src = g_wpack + (size_t)(c + 1) * B_CHUNK_U16X;
            uint32_t d = stb + (buf ^ 1) * ST_SIZE + B_HI;
#pragma unroll
            for (int t = 0; t < 3; ++t) {
                int idx = tid + t * 512;
                if (idx < B_CHUNK_U16X) CP_ASYNC16(d + idx * 16, src + idx);
            }
            CP_COMMIT();
            const int koff = (c + 1) * KC;
#pragma unroll
            for (int t = 0; t < 2; ++t) {
                const float4* p = (const float4*)(x + (size_t)(tok0 + arow + t * 64) * DIM + koff + au * 8);
                ar[2*t]   = p[0];
                ar[2*t+1] = p[1];
            }
        }

#pragma unroll
        for (int ks = 0; ks < 4; ++ks) {
            const uint32_t ko = ks * 32;
            uint32_t ah[4];
            ldsm_x4(ah, sb + A_HI + a_lane + ko);
            uint32_t bh[4][4];
#pragma unroll
            for (int p = 0; p < 4; ++p)
                ldsm_x4(bh[p], sb + B_HI + b_lane + p * 16 * PADB + ko);
#pragma unroll
            for (int p = 0; p < 4; ++p)
#pragma unroll
                for (int h = 0; h < 2; ++h)
                    mma16816h(acc[2 * p + h], ah, bh[p][h], bh[p][2 + h]);
        }

        if (pf) {
#pragma unroll
            for (int t = 0; t < 2; ++t) {
                int r = arow + t * 64;
                *(uint4*)(stn + A_HI + r * PADB + au * 16) = cvt8h(ar[2*t], ar[2*t+1]);
            }
            CP_WAIT0();
        }
        __syncthreads();
    }

    // ---------------- epilogue (overlay) ----------------
    float* smf = (float*)st_ptr;
    const int LSTR = 129;
    const int LOGI = 0;                       // [128][129]: 0-63 gate logits, 64-127 noise->sd
    const int V2O  = 128 * 129;
    const int V3O  = V2O + 128, W1O = V3O + 128, W2O = W1O + 128;
    const int I1O  = W2O + 128, I2O = I1O + 128;
    const int IMPO = I2O + 128, LDO = IMPO + 512;   // [8][64] each
    const int FLGO = LDO + 512;                     // [128] ints

#pragma unroll
    for (int nt = 0; nt < 8; ++nt)
#pragma unroll
        for (int ci = 0; ci < 4; ++ci) {
            int row = wm * 16 + (lane >> 2) + (ci >> 1) * 8;
            int col = wn * 64 + nt * 8 + (lane & 3) * 2 + (ci & 1);
            smf[LOGI + row * LSTR + col] = acc[nt][ci];
        }
    __syncthreads();

    // E1: approx decision + flag near-ties; spill approx data for flagged
    if (tid < TOK_BLK) {
        const int t = tid;
        const float* nrow = noise + (size_t)(tok0 + t) * NEXP;
        float v1 = -CUDART_INF_F, v2 = -CUDART_INF_F, v3 = -CUDART_INF_F;
        int i1 = 0, i2 = 0;
#pragma unroll 4
        for (int e = 0; e < NEXP; ++e) {
            float lg = smf[LOGI + t * LSTR + e];
            float nl = smf[LOGI + t * LSTR + NEXP + e];
            float sp = fmaxf(nl, 0.f) + log1pf(expf(-fabsf(nl)));
            float sd = sp + EPS;
            smf[LOGI + t * LSTR + NEXP + e] = sd;     // overwrite with noise_std
            float nz = fmaf(nrow[e], sd, lg);
            if (nz > v1)      { v3 = v2; v2 = v1; i2 = i1; v1 = nz; i1 = e; }
            else if (nz > v2) { v3 = v2; v2 = nz; i2 = e; }
            else if (nz > v3) { v3 = nz; }
        }
        float ed  = expf(v2 - v1);
        float inv = 1.f / (1.f + ed);
        float w1 = inv, w2 = ed * inv;

        const int tg = tok0 + t;
        int flag = ((v1 - v2) < FIX_THR) || ((v2 - v3) < FIX_THR);
        out[2 * tg]                    = (float)i1;
        out[2 * tg + 1]                = (float)i2;
        out[2 * N_TOKENS + 2 * tg]     = w1;
        out[2 * N_TOKENS + 2 * tg + 1] = w2;
        out[4 * N_TOKENS + tg]         = w1;
        g_flag[tg] = (unsigned char)flag;
        ((int*)(smf + FLGO))[t] = flag;
        if (flag) {
            for (int e = 0; e < NEXP; ++e) {
                g_lgap[(size_t)tg * NEXP + e] = smf[LOGI + t * LSTR + e];
                g_sdap[(size_t)tg * NEXP + e] = smf[LOGI + t * LSTR + NEXP + e];
            }
        }
        smf[V2O + t] = v2; smf[V3O + t] = v3;
        smf[W1O + t] = w1; smf[W2O + t] = w2;
        ((int*)(smf + I1O))[t] = i1; ((int*)(smf + I2O))[t] = i2;
    }
    __syncthreads();

    // E2: partials, skipping flagged (fixup adds exact contributions)
    {
        const int e = tid & 63, g = tid >> 6;
        float imp = 0.f, ld = 0.f;
#pragma unroll 4
        for (int t = g * 16; t < g * 16 + 16; ++t) {
            if (((int*)(smf + FLGO))[t]) continue;
            int ii1 = ((int*)(smf + I1O))[t], ii2 = ((int*)(smf + I2O))[t];
            bool in1 = (ii1 == e), in2 = (ii2 == e);
            if (in1) imp += smf[W1O + t];
            if (in2) imp += smf[W2O + t];
            float kth = (in1 || in2) ? smf[V3O + t] : smf[V2O + t];
            float sd  = smf[LOGI + t * LSTR + NEXP + e];
            float lg  = smf[LOGI + t * LSTR + e];
            float z   = (lg - kth) / (sd + EPS);
            ld += 0.5f * (1.f + erff(z * 0.70710678118654752f));
        }
        smf[IMPO + g * 64 + e] = imp;
        smf[LDO  + g * 64 + e] = ld;
    }
    __syncthreads();

    if (tid < NEXP) {
        float si = 0.f, sl = 0.f;
#pragma unroll
        for (int g = 0; g < 8; ++g) { si += smf[IMPO + g * 64 + tid]; sl += smf[LDO + g * 64 + tid]; }
        g_imp_part [blockIdx.x * NEXP + tid] = si;
        g_load_part[blockIdx.x * NEXP + tid] = sl;
    }
}

// ======================= fixup: warp-per-flagged-token, candidate-only exact dots =======================
__global__ void __launch_bounds__(256)
router_fixup_kernel(const float* __restrict__ x, const float* __restrict__ noise,
                    const float* __restrict__ Wg, const float* __restrict__ Wn,
                    float* __restrict__ out)
{
    __shared__ int   list[TOK_BLK];
    __shared__ int   nflag_s;
    __shared__ float wimp[8][64], wload[8][64];
    const int tid  = threadIdx.x;
    const int wid  = tid >> 5;
    const int lane = tid & 31;
    const int base = blockIdx.x * TOK_BLK;

    if (tid == 0) {
        int n = 0;
        for (int t = 0; t < TOK_BLK; ++t)
            if (g_flag[base + t]) list[n++] = base + t;
        nflag_s = n;
    }
    wimp[wid][lane] = 0.f; wimp[wid][lane + 32] = 0.f;
    wload[wid][lane] = 0.f; wload[wid][lane + 32] = 0.f;
    __syncthreads();
    const int nflag = nflag_s;
    if (nflag == 0) return;

    for (int idx = wid; idx < nflag; idx += 8) {
        const int t = list[idx];
        // approx data: lane handles experts lane and lane+32
        float lga[2], sda[2], nza[2];
#pragma unroll
        for (int j = 0; j < 2; ++j) {
            int e = lane + 32 * j;
            lga[j] = g_lgap[(size_t)t * NEXP + e];
            sda[j] = g_sdap[(size_t)t * NEXP + e];
            nza[j] = fmaf(noise[(size_t)t * NEXP + e], sda[j], lga[j]);
        }
        // approx 3rd max via 3 argmax-exclude passes
        float c0 = nza[0], c1 = nza[1];
        float v3a = -CUDART_INF_F;
#pragma unroll
        for (int pass = 0; pass < 3; ++pass) {
            float m  = fmaxf(c0, c1);
            int  mid = (c0 >= c1) ? (lane * 2) : (lane * 2 + 1);
#pragma unroll
            for (int o = 16; o > 0; o >>= 1) {
                float mv = __shfl_xor_sync(0xFFFFFFFFu, m, o);
                int   mi = __shfl_xor_sync(0xFFFFFFFFu, mid, o);
                if (mv > m || (mv == m && mi < mid)) { m = mv; mid = mi; }
            }
            v3a = m;
            if (mid == lane * 2)     c0 = -CUDART_INF_F;
            if (mid == lane * 2 + 1) c1 = -CUDART_INF_F;
        }
        const float thr = v3a - WINDOW;
        unsigned mask0 = __ballot_sync(0xFFFFFFFFu, nza[0] >= thr);
        unsigned mask1 = __ballot_sync(0xFFFFFFFFu, nza[1] >= thr);

        const float* xr = x + (size_t)t * DIM;
        float v1x = -CUDART_INF_F, v2x = -CUDART_INF_F, v3x = -CUDART_INF_F;
        int i1 = 0, i2 = 0;

#pragma unroll 1
        for (int half = 0; half < 2; ++half) {
            unsigned m = half ? mask1 : mask0;
            while (m) {
                int e = __ffs(m) - 1 + half * 32;
                m &= m - 1;
                const float* wg = Wg + (size_t)e * DIM;
                const float* wn = Wn + (size_t)e * DIM;
                float sg = 0.f, sn = 0.f;
#pragma unroll
                for (int jj = 0; jj < 16; ++jj) {
                    int k = lane * 4 + jj * 128;
                    float4 xv = *(const float4*)(xr + k);
                    float4 g4 = *(const float4*)(wg + k);
                    float4 n4 = *(const float4*)(wn + k);
                    sg = fmaf(xv.x, g4.x, fmaf(xv.y, g4.y, fmaf(xv.z, g4.z, fmaf(xv.w, g4.w, sg))));
                    sn = fmaf(xv.x, n4.x, fmaf(xv.y, n4.y, fmaf(xv.z, n4.z, fmaf(xv.w, n4.w, sn))));
                }
#pragma unroll
                for (int o = 16; o > 0; o >>= 1) {
                    sg += __shfl_xor_sync(0xFFFFFFFFu, sg, o);
                    sn += __shfl_xor_sync(0xFFFFFFFFu, sn, o);
                }
                float sp  = fmaxf(sn, 0.f) + log1pf(expf(-fabsf(sn)));
                float sdx = sp + EPS;
                float nzx = fmaf(noise[(size_t)t * NEXP + e], sdx, sg);
                if (nzx > v1x)      { v3x = v2x; v2x = v1x; i2 = i1; v1x = nzx; i1 = e; }
                else if (nzx > v2x) { v3x = v2x; v2x = nzx; i2 = e; }
                else if (nzx > v3x) { v3x = nzx; }
            }
        }

        float ed  = expf(v2x - v1x);
        float inv = 1.f / (1.f + ed);
        float w1 = inv, w2 = ed * inv;
        if (lane == 0) {
            out[2 * t]                    = (float)i1;
            out[2 * t + 1]                = (float)i2;
            out[2 * N_TOKENS + 2 * t]     = w1;
            out[2 * N_TOKENS + 2 * t + 1] = w2;
            out[4 * N_TOKENS + t]         = w1;
            wimp[wid][i1] += w1;
            wimp[wid][i2] += w2;
        }
#pragma unroll
        for (int j = 0; j < 2; ++j) {
            int e = lane + 32 * j;
            float kth = (e == i1 || e == i2) ? v3x : v2x;
            float z = (lga[j] - kth) / (sda[j] + EPS);
            wload[wid][e] += 0.5f * (1.f + erff(z * 0.70710678118654752f));
        }
    }
    __syncthreads();

    if (tid < NEXP) {
        float si = 0.f, sl = 0.f;
#pragma unroll
        for (int q = 0; q < 8; ++q) { si += wimp[q][tid]; sl += wload[q][tid]; }
        g_imp_part [blockIdx.x * NEXP + tid] += si;
        g_load_part[blockIdx.x * NEXP + tid] += sl;
    }
}

// ======================= finalize =======================
__global__ void __launch_bounds__(512) router_finalize_kernel(float* __restrict__ out)
{
    __shared__ float pimp[8][64], pld[8][64];
    const int tid = threadIdx.x;
    const int e = tid & 63, g = tid >> 6;
    float si = 0.f, sl = 0.f;
#pragma unroll
    for (int b = g; b < NBLOCKS; b += 8) {
        si += g_imp_part [b * NEXP + e];
        sl += g_load_part[b * NEXP + e];
    }
    pimp[g][e] = si; pld[g][e] = sl;
    __syncthreads();
    if (tid < 64) {
        float a = 0.f, b = 0.f;
#pragma unroll
        for (int q = 0; q < 8; ++q) { a += pimp[q][tid]; b += pld[q][tid]; }
        pimp[0][tid] = a; pld[0][tid] = b;
    }
    __syncthreads();
    if (tid == 0) {
        float mi = 0.f, ml = 0.f;
        for (int q = 0; q < NEXP; ++q) { mi += pimp[0][q]; ml += pld[0][q]; }
        mi *= (1.f / NEXP); ml *= (1.f / NEXP);
        float vi = 0.f, vl = 0.f;
        for (int q = 0; q < NEXP; ++q) {
            float di = pimp[0][q] - mi, dl = pld[0][q] - ml;
            vi += di * di; vl += dl * dl;
        }
        vi *= (1.f / NEXP); vl *= (1.f / NEXP);
        out[5 * N_TOKENS] = 0.1f * (vi / (mi * mi + EPS)) + 0.1f * (vl / (ml * ml + EPS));
    }
}

extern "C" void kernel_launch(void* const* d_in, const int* in_sizes, int n_in,
                              void* d_out, int out_size)
{
    const float* x     = (const float*)d_in[0];
    const float* noise = (const float*)d_in[1];
    const float* Wg    = (const float*)d_in[2];
    const float* Wn    = (const float*)d_in[3];
    float* out = (float*)d_out;

    cudaFuncSetAttribute(router_main_kernel,
                         cudaFuncAttributeMaxDynamicSharedMemorySize, SMEM_BYTES);
    wpack_kernel<<<128, 256>>>(Wg, Wn);
    router_main_kernel<<<NBLOCKS, NTHREADS, SMEM_BYTES>>>(x, noise, out);
    router_fixup_kernel<<<NBLOCKS, 256>>>(x, noise, Wg, Wn, out);
    router_finalize_kernel<<<1, 512>>>(out);
}

// round 11
// speedup vs baseline: 16.1024x; 1.0025x over previous
#include <cuda_runtime.h>
#include <cuda_fp16.h>
#include <math_constants.h>
#include <cstdint>

#define N_TOKENS   16384
#define DIM        2048
#define NEXP       64
#define NCOLS      128
#define TOK_BLK    128
#define NBLOCKS    (N_TOKENS / TOK_BLK)   // 128
#define NTHREADS   512
#define KC         64
#define NCHUNK     (DIM / KC)             // 32
#define EPS        1e-9f
#define FIX_THR    4e-3f
#define WINDOW     8e-3f

#define PADB       144
#define TILE_BYTES (128 * PADB)           // 18432
#define A_HI       0
#define B_HI       TILE_BYTES
#define ST_SIZE    (2 * TILE_BYTES)       // 36864
#define B_CHUNK_U16X (TILE_BYTES / 16)    // 1152
#define SMEM_BYTES (1024 + 2 * ST_SIZE)

// ---- static device scratch ----
__device__ uint4 g_wpack[NCHUNK * B_CHUNK_U16X];   // 576KB fp16 W
__device__ float g_imp_part [NBLOCKS * NEXP];
__device__ float g_load_part[NBLOCKS * NEXP];
__device__ unsigned char g_flag[N_TOKENS];
__device__ float g_lgap[N_TOKENS * NEXP];          // approx gate logits (flagged only)
__device__ float g_sdap[N_TOKENS * NEXP];          // approx noise_std   (flagged only)
__device__ unsigned int g_ticket;

// ======================= helpers =======================
__device__ __forceinline__ uint32_t smem_u32(const void* p) {
    uint32_t a;
    asm("{ .reg .u64 t; cvta.to.shared.u64 t, %1; cvt.u32.u64 %0, t; }" : "=r"(a) : "l"(p));
    return a;
}
__device__ __forceinline__ void ldsm_x4(uint32_t (&r)[4], uint32_t addr) {
    asm volatile("ldmatrix.sync.aligned.m8n8.x4.shared.b16 {%0,%1,%2,%3}, [%4];"
                 : "=r"(r[0]), "=r"(r[1]), "=r"(r[2]), "=r"(r[3]) : "r"(addr));
}
__device__ __forceinline__ void mma16816h(float* d, const uint32_t* a, uint32_t b0, uint32_t b1) {
    asm volatile("mma.sync.aligned.m16n8k16.row.col.f32.f16.f16.f32 "
                 "{%0,%1,%2,%3}, {%4,%5,%6,%7}, {%8,%9}, {%0,%1,%2,%3};"
                 : "+f"(d[0]), "+f"(d[1]), "+f"(d[2]), "+f"(d[3])
                 : "r"(a[0]), "r"(a[1]), "r"(a[2]), "r"(a[3]), "r"(b0), "r"(b1));
}
#define CP_ASYNC16(dst, src) \
    asm volatile("cp.async.cg.shared.global [%0], [%1], 16;" :: "r"(dst), "l"(src))
#define CP_COMMIT()  asm volatile("cp.async.commit_group;")
#define CP_WAIT0()   asm volatile("cp.async.wait_group 0;")

__device__ __forceinline__ uint4 cvt8h(float4 a, float4 b) {
    __half2 h0 = __floats2half2_rn(a.x, a.y);
    __half2 h1 = __floats2half2_rn(a.z, a.w);
    __half2 h2 = __floats2half2_rn(b.x, b.y);
    __half2 h3 = __floats2half2_rn(b.z, b.w);
    uint4 r;
    r.x = *reinterpret_cast<uint32_t*>(&h0);
    r.y = *reinterpret_cast<uint32_t*>(&h1);
    r.z = *reinterpret_cast<uint32_t*>(&h2);
    r.w = *reinterpret_cast<uint32_t*>(&h3);
    return r;
}

// ======================= W precompute (+ticket reset) =======================
__global__ void __launch_bounds__(256) wpack_kernel(const float* __restrict__ Wg,
                                                    const float* __restrict__ Wn) {
    if (blockIdx.x == 0 && threadIdx.x == 0) g_ticket = 0u;
    int id = blockIdx.x * 256 + threadIdx.x;
    int chunk = id >> 10;
    int rem   = id & 1023;
    int col = rem >> 3, u = rem & 7;
    const float* src = (col < NEXP ? Wg + (size_t)col * DIM : Wn + (size_t)(col - NEXP) * DIM)
                       + chunk * KC + u * 8;
    float4 a = ((const float4*)src)[0];
    float4 b = ((const float4*)src)[1];
    char* base = (char*)g_wpack + (size_t)chunk * TILE_BYTES;
    *(uint4*)(base + col * PADB + u * 16) = cvt8h(a, b);
}

// ======================= main: fp16 1-pass GEMM + approx epilogue =======================
__global__ void __launch_bounds__(NTHREADS)
router_main_kernel(const float* __restrict__ x,
                   const float* __restrict__ noise,
                   float* __restrict__ out)
{
    extern __shared__ char sm[];
    const uint32_t smb = smem_u32(sm);
    const uint32_t stb = (smb + 1023u) & ~1023u;
    char* st_ptr = sm + (stb - smb);

    const int tid  = threadIdx.x;
    const int wid  = tid >> 5;
    const int lane = tid & 31;
    const int wm   = wid >> 1;
    const int wn   = wid & 1;
    const int tok0 = blockIdx.x * TOK_BLK;

    const int arow = tid >> 3, au = tid & 7;

    float acc[8][4];
#pragma unroll
    for (int j = 0; j < 8; ++j)
#pragma unroll
        for (int q = 0; q < 4; ++q) acc[j][q] = 0.f;

    // ---- prologue ----
    {
        const uint4* src = g_wpack;
        uint32_t d = stb + B_HI;
#pragma unroll
        for (int t = 0; t < 3; ++t) {
            int idx = tid + t * 512;
            if (idx < B_CHUNK_U16X) CP_ASYNC16(d + idx * 16, src + idx);
        }
        CP_COMMIT();

        float4 ar[4];
#pragma unroll
        for (int t = 0; t < 2; ++t) {
            const float4* p = (const float4*)(x + (size_t)(tok0 + arow + t * 64) * DIM + au * 8);
            ar[2*t]   = p[0];
            ar[2*t+1] = p[1];
        }
#pragma unroll
        for (int t = 0; t < 2; ++t) {
            int r = arow + t * 64;
            *(uint4*)(st_ptr + A_HI + r * PADB + au * 16) = cvt8h(ar[2*t], ar[2*t+1]);
        }
        CP_WAIT0();
        __syncthreads();
    }

    const uint32_t a_lane = (uint32_t)((wm * 16 + (lane & 15)) * PADB + (lane >> 4) * 16);
    const uint32_t b_lane = (uint32_t)((wn * 64 + (lane & 15)) * PADB + (lane >> 4) * 16);

    for (int c = 0; c < NCHUNK; ++c) {
        const int buf = c & 1;
        const uint32_t sb = stb + buf * ST_SIZE;
        const bool pf = (c + 1 < NCHUNK);
        char* stn = st_ptr + (buf ^ 1) * ST_SIZE;

        float4 ar[4];
        if (pf) {
            const uint4* src = g_wpack + (size_t)(c + 1) * B_CHUNK_U16X;
            uint32_t d = stb + (buf ^ 1) * ST_SIZE + B_HI;
#pragma unroll
            for (int t = 0; t < 3; ++t) {
                int idx = tid + t * 512;
                if (idx < B_CHUNK_U16X) CP_ASYNC16(d + idx * 16, src + idx);
            }
            CP_COMMIT();
            const int koff = (c + 1) * KC;
#pragma unroll
            for (int t = 0; t < 2; ++t) {
                const float4* p = (const float4*)(x + (size_t)(tok0 + arow + t * 64) * DIM + koff + au * 8);
                ar[2*t]   = p[0];
                ar[2*t+1] = p[1];
            }
        }

#pragma unroll
        for (int ks = 0; ks < 4; ++ks) {
            const uint32_t ko = ks * 32;
            uint32_t ah[4];
            ldsm_x4(ah, sb + A_HI + a_lane + ko);
            uint32_t bh[4][4];
#pragma unroll
            for (int p = 0; p < 4; ++p)
                ldsm_x4(bh[p], sb + B_HI + b_lane + p * 16 * PADB + ko);
#pragma unroll
            for (int p = 0; p < 4; ++p)
#pragma unroll
                for (int h = 0; h < 2; ++h)
                    mma16816h(acc[2 * p + h], ah, bh[p][h], bh[p][2 + h]);
        }

        if (pf) {
#pragma unroll
            for (int t = 0; t < 2; ++t) {
                int r = arow + t * 64;
                *(uint4*)(stn + A_HI + r * PADB + au * 16) = cvt8h(ar[2*t], ar[2*t+1]);
            }
            CP_WAIT0();
        }
        __syncthreads();
    }

    // ---------------- epilogue (overlay) ----------------
    float* smf = (float*)st_ptr;
    const int LSTR = 129;
    const int LOGI = 0;                       // [128][129]: 0-63 gate logits, 64-127 noise->sd
    const int V2O  = 128 * 129;
    const int V3O  = V2O + 128, W1O = V3O + 128, W2O = W1O + 128;
    const int I1O  = W2O + 128, I2O = I1O + 128;
    const int IMPO = I2O + 128, LDO = IMPO + 512;   // [8][64] each
    const int FLGO = LDO + 512;                     // [128] ints

#pragma unroll
    for (int nt = 0; nt < 8; ++nt)
#pragma unroll
        for (int ci = 0; ci < 4; ++ci) {
            int row = wm * 16 + (lane >> 2) + (ci >> 1) * 8;
            int col = wn * 64 + nt * 8 + (lane & 3) * 2 + (ci & 1);
            smf[LOGI + row * LSTR + col] = acc[nt][ci];
        }
    __syncthreads();

    // E1: approx decision + flag near-ties; spill approx data for flagged
    if (tid < TOK_BLK) {
        const int t = tid;
        const float* nrow = noise + (size_t)(tok0 + t) * NEXP;
        float v1 = -CUDART_INF_F, v2 = -CUDART_INF_F, v3 = -CUDART_INF_F;
        int i1 = 0, i2 = 0;
#pragma unroll 4
        for (int e = 0; e < NEXP; ++e) {
            float lg = smf[LOGI + t * LSTR + e];
            float nl = smf[LOGI + t * LSTR + NEXP + e];
            float sp = fmaxf(nl, 0.f) + log1pf(expf(-fabsf(nl)));
            float sd = sp + EPS;
            smf[LOGI + t * LSTR + NEXP + e] = sd;     // overwrite with noise_std
            float nz = fmaf(nrow[e], sd, lg);
            if (nz > v1)      { v3 = v2; v2 = v1; i2 = i1; v1 = nz; i1 = e; }
            else if (nz > v2) { v3 = v2; v2 = nz; i2 = e; }
            else if (nz > v3) { v3 = nz; }
        }
        float ed  = expf(v2 - v1);
        float inv = 1.f / (1.f + ed);
        float w1 = inv, w2 = ed * inv;

        const int tg = tok0 + t;
        int flag = ((v1 - v2) < FIX_THR) || ((v2 - v3) < FIX_THR);
        out[2 * tg]                    = (float)i1;
        out[2 * tg + 1]                = (float)i2;
        out[2 * N_TOKENS + 2 * tg]     = w1;
        out[2 * N_TOKENS + 2 * tg + 1] = w2;
        out[4 * N_TOKENS + tg]         = w1;
        g_flag[tg] = (unsigned char)flag;
        ((int*)(smf + FLGO))[t] = flag;
        if (flag) {
            for (int e = 0; e < NEXP; ++e) {
                g_lgap[(size_t)tg * NEXP + e] = smf[LOGI + t * LSTR + e];
                g_sdap[(size_t)tg * NEXP + e] = smf[LOGI + t * LSTR + NEXP + e];
            }
        }
        smf[V2O + t] = v2; smf[V3O + t] = v3;
        smf[W1O + t] = w1; smf[W2O + t] = w2;
        ((int*)(smf + I1O))[t] = i1; ((int*)(smf + I2O))[t] = i2;
    }
    __syncthreads();

    // E2: partials, skipping flagged (fixup adds exact contributions)
    {
        const int e = tid & 63, g = tid >> 6;
        float imp = 0.f, ld = 0.f;
#pragma unroll 4
        for (int t = g * 16; t < g * 16 + 16; ++t) {
            if (((int*)(smf + FLGO))[t]) continue;
            int ii1 = ((int*)(smf + I1O))[t], ii2 = ((int*)(smf + I2O))[t];
            bool in1 = (ii1 == e), in2 = (ii2 == e);
            if (in1) imp += smf[W1O + t];
            if (in2) imp += smf[W2O + t];
            float kth = (in1 || in2) ? smf[V3O + t] : smf[V2O + t];
            float sd  = smf[LOGI + t * LSTR + NEXP + e];
            float lg  = smf[LOGI + t * LSTR + e];
            float z   = (lg - kth) / (sd + EPS);
            ld += 0.5f * (1.f + erff(z * 0.70710678118654752f));
        }
        smf[IMPO + g * 64 + e] = imp;
        smf[LDO  + g * 64 + e] = ld;
    }
    __syncthreads();

    if (tid < NEXP) {
        float si = 0.f, sl = 0.f;
#pragma unroll
        for (int g = 0; g < 8; ++g) { si += smf[IMPO + g * 64 + tid]; sl += smf[LDO + g * 64 + tid]; }
        g_imp_part [blockIdx.x * NEXP + tid] = si;
        g_load_part[blockIdx.x * NEXP + tid] = sl;
    }
}

// ======================= fixup + fused finalize =======================
__global__ void __launch_bounds__(256)
router_fixup_kernel(const float* __restrict__ x, const float* __restrict__ noise,
                    const float* __restrict__ Wg, const float* __restrict__ Wn,
                    float* __restrict__ out)
{
    __shared__ int   list[TOK_BLK];
    __shared__ int   nflag_s;
    __shared__ float wimp[8][64], wload[8][64];
    const int tid  = threadIdx.x;
    const int wid  = tid >> 5;
    const int lane = tid & 31;
    const int base = blockIdx.x * TOK_BLK;

    if (tid == 0) {
        int n = 0;
        for (int t = 0; t < TOK_BLK; ++t)
            if (g_flag[base + t]) list[n++] = base + t;
        nflag_s = n;
    }
    wimp[wid][lane] = 0.f; wimp[wid][lane + 32] = 0.f;
    wload[wid][lane] = 0.f; wload[wid][lane + 32] = 0.f;
    __syncthreads();
    const int nflag = nflag_s;

    for (int idx = wid; idx < nflag; idx += 8) {
        const int t = list[idx];
        float lga[2], sda[2], nza[2];
#pragma unroll
        for (int j = 0; j < 2; ++j) {
            int e = lane + 32 * j;
            lga[j] = g_lgap[(size_t)t * NEXP + e];
            sda[j] = g_sdap[(size_t)t * NEXP + e];
            nza[j] = fmaf(noise[(size_t)t * NEXP + e], sda[j], lga[j]);
        }
        // approx 3rd max via 3 argmax-exclude passes
        float c0 = nza[0], c1 = nza[1];
        float v3a = -CUDART_INF_F;
#pragma unroll
        for (int pass = 0; pass < 3; ++pass) {
            float m  = fmaxf(c0, c1);
            int  mid = (c0 >= c1) ? (lane * 2) : (lane * 2 + 1);
#pragma unroll
            for (int o = 16; o > 0; o >>= 1) {
                float mv = __shfl_xor_sync(0xFFFFFFFFu, m, o);
                int   mi = __shfl_xor_sync(0xFFFFFFFFu, mid, o);
                if (mv > m || (mv == m && mi < mid)) { m = mv; mid = mi; }
            }
            v3a = m;
            if (mid == lane * 2)     c0 = -CUDART_INF_F;
            if (mid == lane * 2 + 1) c1 = -CUDART_INF_F;
        }
        const float thr = v3a - WINDOW;
        unsigned mask0 = __ballot_sync(0xFFFFFFFFu, nza[0] >= thr);
        unsigned mask1 = __ballot_sync(0xFFFFFFFFu, nza[1] >= thr);

        const float* xr = x + (size_t)t * DIM;
        float v1x = -CUDART_INF_F, v2x = -CUDART_INF_F, v3x = -CUDART_INF_F;
        int i1 = 0, i2 = 0;

#pragma unroll 1
        for (int half = 0; half < 2; ++half) {
            unsigned m = half ? mask1 : mask0;
            while (m) {
                int e = __ffs(m) - 1 + half * 32;
                m &= m - 1;
                const float* wg = Wg + (size_t)e * DIM;
                const float* wn = Wn + (size_t)e * DIM;
                float sg = 0.f, sn = 0.f;
#pragma unroll
                for (int jj = 0; jj < 16; ++jj) {
                    int k = lane * 4 + jj * 128;
                    float4 xv = *(const float4*)(xr + k);
                    float4 g4 = *(const float4*)(wg + k);
                    float4 n4 = *(const float4*)(wn + k);
                    sg = fmaf(xv.x, g4.x, fmaf(xv.y, g4.y, fmaf(xv.z, g4.z, fmaf(xv.w, g4.w, sg))));
                    sn = fmaf(xv.x, n4.x, fmaf(xv.y, n4.y, fmaf(xv.z, n4.z, fmaf(xv.w, n4.w, sn))));
                }
#pragma unroll
                for (int o = 16; o > 0; o >>= 1) {
                    sg += __shfl_xor_sync(0xFFFFFFFFu, sg, o);
                    sn += __shfl_xor_sync(0xFFFFFFFFu, sn, o);
                }
                float sp  = fmaxf(sn, 0.f) + log1pf(expf(-fabsf(sn)));
                float sdx = sp + EPS;
                float nzx = fmaf(noise[(size_t)t * NEXP + e], sdx, sg);
                if (nzx > v1x)      { v3x = v2x; v2x = v1x; i2 = i1; v1x = nzx; i1 = e; }
                else if (nzx > v2x) { v3x = v2x; v2x = nzx; i2 = e; }
                else if (nzx > v3x) { v3x = nzx; }
            }
        }

        float ed  = expf(v2x - v1x);
        float inv = 1.f / (1.f + ed);
        float w1 = inv, w2 = ed * inv;
        if (lane == 0) {
            out[2 * t]                    = (float)i1;
            out[2 * t + 1]                = (float)i2;
            out[2 * N_TOKENS + 2 * t]     = w1;
            out[2 * N_TOKENS + 2 * t + 1] = w2;
            out[4 * N_TOKENS + t]         = w1;
            wimp[wid][i1] += w1;
            wimp[wid][i2] += w2;
        }
#pragma unroll
        for (int j = 0; j < 2; ++j) {
            int e = lane + 32 * j;
            float kth = (e == i1 || e == i2) ? v3x : v2x;
            float z = (lga[j] - kth) / (sda[j] + EPS);
            wload[wid][e] += 0.5f * (1.f + erff(z * 0.70710678118654752f));
        }
    }
    __syncthreads();

    if (tid < NEXP) {
        float si = 0.f, sl = 0.f;
#pragma unroll
        for (int q = 0; q < 8; ++q) { si += wimp[q][tid]; sl += wload[q][tid]; }
        g_imp_part [blockIdx.x * NEXP + tid] += si;
        g_load_part[blockIdx.x * NEXP + tid] += sl;
    }

    // ---- fused finalize: last block to arrive computes aux ----
    __threadfence();
    __shared__ int lastflag;
    if (tid == 0) {
        unsigned tk = atomicAdd(&g_ticket, 1u);
        lastflag = (tk == (unsigned)(NBLOCKS - 1));
    }
    __syncthreads();
    if (!lastflag) return;

    __shared__ float fimp[4][64], fld[4][64];
    {
        const int e = tid & 63, g = tid >> 6;   // 4 groups x 32 blocks
        float si = 0.f, sl = 0.f;
        for (int b = g; b < NBLOCKS; b += 4) {
            si += g_imp_part [b * NEXP + e];
            sl += g_load_part[b * NEXP + e];
        }
        fimp[g][e] = si; fld[g][e] = sl;
    }
    __syncthreads();
    __shared__ float timp[64], tld[64];
    if (tid < 64) {
        timp[tid] = fimp[0][tid] + fimp[1][tid] + fimp[2][tid] + fimp[3][tid];
        tld[tid]  = fld[0][tid]  + fld[1][tid]  + fld[2][tid]  + fld[3][tid];
    }
    __syncthreads();
    if (tid < 32) {
        float ai = timp[tid] + timp[tid + 32];
        float al = tld[tid]  + tld[tid + 32];
        float si = ai, sl = al;
#pragma unroll
        for (int o = 16; o > 0; o >>= 1) {
            si += __shfl_xor_sync(0xFFFFFFFFu, si, o);
            sl += __shfl_xor_sync(0xFFFFFFFFu, sl, o);
        }
        float mi = si * (1.f / NEXP), ml = sl * (1.f / NEXP);
        float d0 = timp[tid] - mi, d1 = timp[tid + 32] - mi;
        float e0 = tld[tid]  - ml, e1 = tld[tid + 32]  - ml;
        float vi = d0 * d0 + d1 * d1;
        float vl = e0 * e0 + e1 * e1;
#pragma unroll
        for (int o = 16; o > 0; o >>= 1) {
            vi += __shfl_xor_sync(0xFFFFFFFFu, vi, o);
            vl += __shfl_xor_sync(0xFFFFFFFFu, vl, o);
        }
        vi *= (1.f / NEXP); vl *= (1.f / NEXP);
        if (tid == 0)
            out[5 * N_TOKENS] = 0.1f * (vi / (mi * mi + EPS)) + 0.1f * (vl / (ml * ml + EPS));
    }
}

extern "C" void kernel_launch(void* const* d_in, const int* in_sizes, int n_in,
                              void* d_out, int out_size)
{
    const float* x     = (const float*)d_in[0];
    const float* noise = (const float*)d_in[1];
    const float* Wg    = (const float*)d_in[2];
    const float* Wn    = (const float*)d_in[3];
    float* out = (float*)d_out;

    cudaFuncSetAttribute(router_main_kernel,
                         cudaFuncAttributeMaxDynamicSharedMemorySize, SMEM_BYTES);
    wpack_kernel<<<128, 256>>>(Wg, Wn);
    router_main_kernel<<<NBLOCKS, NTHREADS, SMEM_BYTES>>>(x, noise, out);
    router_fixup_kernel<<<NBLOCKS, 256>>>(x, noise, Wg, Wn, out);
}

// round 12
// speedup vs baseline: 16.5074x; 1.0252x over previous
#include <cuda_runtime.h>
#include <cuda_fp16.h>
#include <math_constants.h>
#include <cstdint>

#define N_TOKENS   16384
#define DIM        2048
#define NEXP       64
#define NCOLS      128
#define NBLK       148
#define BIGB       136               // blocks with 112 tokens; rest have 96
#define ROWS_BIG   112
#define ROWS_SMALL 96
#define NTHREADS   512
#define KC         64
#define NCHUNK     (DIM / KC)        // 32
#define EPS        1e-9f
#define FIX_THR    4e-3f
#define WINDOW     8e-3f

#define PADB       144
#define TILE_BYTES (128 * PADB)      // 18432
#define A_HI       0
#define B_HI       TILE_BYTES
#define ST_SIZE    (2 * TILE_BYTES)  // 36864
#define B_CHUNK_U16X (TILE_BYTES / 16)   // 1152
#define SMEM_BYTES (1024 + 84992)    // covers GEMM stages (73728) and epilogue overlay

// ---- static device scratch ----
__device__ uint4 g_wpack[NCHUNK * B_CHUNK_U16X];   // 576KB fp16 W
__device__ float g_imp_part [NBLK * NEXP];
__device__ float g_load_part[NBLK * NEXP];
__device__ unsigned int g_ticket;

// ======================= helpers =======================
__device__ __forceinline__ uint32_t smem_u32(const void* p) {
    uint32_t a;
    asm("{ .reg .u64 t; cvta.to.shared.u64 t, %1; cvt.u32.u64 %0, t; }" : "=r"(a) : "l"(p));
    return a;
}
__device__ __forceinline__ void ldsm_x4(uint32_t (&r)[4], uint32_t addr) {
    asm volatile("ldmatrix.sync.aligned.m8n8.x4.shared.b16 {%0,%1,%2,%3}, [%4];"
                 : "=r"(r[0]), "=r"(r[1]), "=r"(r[2]), "=r"(r[3]) : "r"(addr));
}
__device__ __forceinline__ void mma16816h(float* d, const uint32_t* a, uint32_t b0, uint32_t b1) {
    asm volatile("mma.sync.aligned.m16n8k16.row.col.f32.f16.f16.f32 "
                 "{%0,%1,%2,%3}, {%4,%5,%6,%7}, {%8,%9}, {%0,%1,%2,%3};"
                 : "+f"(d[0]), "+f"(d[1]), "+f"(d[2]), "+f"(d[3])
                 : "r"(a[0]), "r"(a[1]), "r"(a[2]), "r"(a[3]), "r"(b0), "r"(b1));
}
#define CP_ASYNC16(dst, src) \
    asm volatile("cp.async.cg.shared.global [%0], [%1], 16;" :: "r"(dst), "l"(src))
#define CP_COMMIT()  asm volatile("cp.async.commit_group;")
#define CP_WAIT0()   asm volatile("cp.async.wait_group 0;")

__device__ __forceinline__ uint4 cvt8h(float4 a, float4 b) {
    __half2 h0 = __floats2half2_rn(a.x, a.y);
    __half2 h1 = __floats2half2_rn(a.z, a.w);
    __half2 h2 = __floats2half2_rn(b.x, b.y);
    __half2 h3 = __floats2half2_rn(b.z, b.w);
    uint4 r;
    r.x = *reinterpret_cast<uint32_t*>(&h0);
    r.y = *reinterpret_cast<uint32_t*>(&h1);
    r.z = *reinterpret_cast<uint32_t*>(&h2);
    r.w = *reinterpret_cast<uint32_t*>(&h3);
    return r;
}

// ======================= W precompute (+ticket reset) =======================
__global__ void __launch_bounds__(256) wpack_kernel(const float* __restrict__ Wg,
                                                    const float* __restrict__ Wn) {
    if (blockIdx.x == 0 && threadIdx.x == 0) g_ticket = 0u;
    int id = blockIdx.x * 256 + threadIdx.x;
    int chunk = id >> 10;
    int rem   = id & 1023;
    int col = rem >> 3, u = rem & 7;
    const float* src = (col < NEXP ? Wg + (size_t)col * DIM : Wn + (size_t)(col - NEXP) * DIM)
                       + chunk * KC + u * 8;
    float4 a = ((const float4*)src)[0];
    float4 b = ((const float4*)src)[1];
    char* base = (char*)g_wpack + (size_t)chunk * TILE_BYTES;
    *(uint4*)(base + col * PADB + u * 16) = cvt8h(a, b);
}

// ======================= main: GEMM + epilogue + fused fixup + finalize =======================
__global__ void __launch_bounds__(NTHREADS)
router_main_kernel(const float* __restrict__ x,
                   const float* __restrict__ noise,
                   const float* __restrict__ Wg,
                   const float* __restrict__ Wn,
                   float* __restrict__ out)
{
    extern __shared__ char sm[];
    const uint32_t smb = smem_u32(sm);
    const uint32_t stb = (smb + 1023u) & ~1023u;
    char* st_ptr = sm + (stb - smb);

    const int tid  = threadIdx.x;
    const int wid  = tid >> 5;
    const int lane = tid & 31;
    const int wm   = wid >> 1;
    const int wn   = wid & 1;
    const int b    = blockIdx.x;
    const int rows = (b < BIGB) ? ROWS_BIG : ROWS_SMALL;
    const int tok0 = (b < BIGB) ? b * ROWS_BIG : BIGB * ROWS_BIG + (b - BIGB) * ROWS_SMALL;

    const int arow = tid >> 3, au = tid & 7;
    const bool do_mma = (wm * 16 < rows);

    float acc[8][4];
#pragma unroll
    for (int j = 0; j < 8; ++j)
#pragma unroll
        for (int q = 0; q < 4; ++q) acc[j][q] = 0.f;

    // ---- prologue ----
    {
        const uint4* src = g_wpack;
        uint32_t d = stb + B_HI;
#pragma unroll
        for (int t = 0; t < 3; ++t) {
            int idx = tid + t * 512;
            if (idx < B_CHUNK_U16X) CP_ASYNC16(d + idx * 16, src + idx);
        }
        CP_COMMIT();

#pragma unroll
        for (int t = 0; t < 2; ++t) {
            int r = arow + t * 64;
            if (r < rows) {
                const float4* p = (const float4*)(x + (size_t)(tok0 + r) * DIM + au * 8);
                *(uint4*)(st_ptr + A_HI + r * PADB + au * 16) = cvt8h(p[0], p[1]);
            }
        }
        CP_WAIT0();
        __syncthreads();
    }

    const uint32_t a_lane = (uint32_t)((wm * 16 + (lane & 15)) * PADB + (lane >> 4) * 16);
    const uint32_t b_lane = (uint32_t)((wn * 64 + (lane & 15)) * PADB + (lane >> 4) * 16);

    for (int c = 0; c < NCHUNK; ++c) {
        const int buf = c & 1;
        const uint32_t sb = stb + buf * ST_SIZE;
        const bool pf = (c + 1 < NCHUNK);
        char* stn = st_ptr + (buf ^ 1) * ST_SIZE;

        float4 ar[4];
        bool aload[2] = {false, false};
        if (pf) {
            const uint4* src = g_wpack + (size_t)(c + 1) * B_CHUNK_U16X;
            uint32_t d = stb + (buf ^ 1) * ST_SIZE + B_HI;
#pragma unroll
            for (int t = 0; t < 3; ++t) {
                int idx = tid + t * 512;
                if (idx < B_CHUNK_U16X) CP_ASYNC16(d + idx * 16, src + idx);
            }
            CP_COMMIT();
            const int koff = (c + 1) * KC;
#pragma unroll
            for (int t = 0; t < 2; ++t) {
                int r = arow + t * 64;
                if (r < rows) {
                    aload[t] = true;
                    const float4* p = (const float4*)(x + (size_t)(tok0 + r) * DIM + koff + au * 8);
                    ar[2*t]   = p[0];
                    ar[2*t+1] = p[1];
                }
            }
        }

        if (do_mma) {
#pragma unroll
            for (int ks = 0; ks < 4; ++ks) {
                const uint32_t ko = ks * 32;
                uint32_t ah[4];
                ldsm_x4(ah, sb + A_HI + a_lane + ko);
                uint32_t bh[4][4];
#pragma unroll
                for (int p = 0; p < 4; ++p)
                    ldsm_x4(bh[p], sb + B_HI + b_lane + p * 16 * PADB + ko);
#pragma unroll
                for (int p = 0; p < 4; ++p)
#pragma unroll
                    for (int h = 0; h < 2; ++h)
                        mma16816h(acc[2 * p + h], ah, bh[p][h], bh[p][2 + h]);
            }
        }

        if (pf) {
#pragma unroll
            for (int t = 0; t < 2; ++t) {
                if (aload[t]) {
                    int r = arow + t * 64;
                    *(uint4*)(stn + A_HI + r * PADB + au * 16) = cvt8h(ar[2*t], ar[2*t+1]);
                }
            }
            CP_WAIT0();
        }
        __syncthreads();
    }

    // ---------------- epilogue (overlay) ----------------
    float* smf = (float*)st_ptr;
    const int LSTR = 129;
    const int LOGI = 0;                       // [128][129]: 0-63 gate logits, 64-127 noise->sd
    const int V2O  = 128 * 129;
    const int V3O  = V2O + 128, W1O = V3O + 128, W2O = W1O + 128;
    const int I1O  = W2O + 128, I2O = I1O + 128;
    const int IMPO = I2O + 128, LDO = IMPO + 512;   // [8][64] each
    const int FLGO = LDO + 512;                     // [128] ints
    const int FIMP = FLGO + 128;                    // [16][64]
    const int FLD2 = FIMP + 1024;                   // [16][64]
    const int LIST = FLD2 + 1024;                   // [128] ints
    const int NFLG = LIST + 128;

#pragma unroll
    for (int nt = 0; nt < 8; ++nt)
#pragma unroll
        for (int ci = 0; ci < 4; ++ci) {
            int row = wm * 16 + (lane >> 2) + (ci >> 1) * 8;
            int col = wn * 64 + nt * 8 + (lane & 3) * 2 + (ci & 1);
            smf[LOGI + row * LSTR + col] = acc[nt][ci];
        }
    // zero fixup accumulators
    smf[FIMP + wid * 64 + lane]      = 0.f;
    smf[FIMP + wid * 64 + lane + 32] = 0.f;
    smf[FLD2 + wid * 64 + lane]      = 0.f;
    smf[FLD2 + wid * 64 + lane + 32] = 0.f;
    __syncthreads();

    // E1: approx decision + flag near-ties
    if (tid < rows) {
        const int t = tid;
        const int tg = tok0 + t;
        const float* nrow = noise + (size_t)tg * NEXP;
        float v1 = -CUDART_INF_F, v2 = -CUDART_INF_F, v3 = -CUDART_INF_F;
        int i1 = 0, i2 = 0;
#pragma unroll 4
        for (int e = 0; e < NEXP; ++e) {
            float lg = smf[LOGI + t * LSTR + e];
            float nl = smf[LOGI + t * LSTR + NEXP + e];
            float sp = fmaxf(nl, 0.f) + log1pf(expf(-fabsf(nl)));
            float sd = sp + EPS;
            smf[LOGI + t * LSTR + NEXP + e] = sd;     // overwrite with noise_std
            float nz = fmaf(nrow[e], sd, lg);
            if (nz > v1)      { v3 = v2; v2 = v1; i2 = i1; v1 = nz; i1 = e; }
            else if (nz > v2) { v3 = v2; v2 = nz; i2 = e; }
            else if (nz > v3) { v3 = nz; }
        }
        float ed  = expf(v2 - v1);
        float inv = 1.f / (1.f + ed);
        float w1 = inv, w2 = ed * inv;

        int flag = ((v1 - v2) < FIX_THR) || ((v2 - v3) < FIX_THR);
        out[2 * tg]                    = (float)i1;
        out[2 * tg + 1]                = (float)i2;
        out[2 * N_TOKENS + 2 * tg]     = w1;
        out[2 * N_TOKENS + 2 * tg + 1] = w2;
        out[4 * N_TOKENS + tg]         = w1;
        ((int*)(smf + FLGO))[t] = flag;
        smf[V2O + t] = v2; smf[V3O + t] = v3;
        smf[W1O + t] = w1; smf[W2O + t] = w2;
        ((int*)(smf + I1O))[t] = i1; ((int*)(smf + I2O))[t] = i2;
    }
    __syncthreads();

    // build flagged-token list
    if (tid == 0) {
        int n = 0;
        for (int t = 0; t < rows; ++t)
            if (((int*)(smf + FLGO))[t]) ((int*)(smf + LIST))[n++] = t;
        ((int*)(smf + NFLG))[0] = n;
    }

    // E2: approx partials, skipping flagged
    {
        const int e = tid & 63, g = tid >> 6;
        float imp = 0.f, ld = 0.f;
        const int tend = min(g * 16 + 16, rows);
        for (int t = g * 16; t < tend; ++t) {
            if (((int*)(smf + FLGO))[t]) continue;
            int ii1 = ((int*)(smf + I1O))[t], ii2 = ((int*)(smf + I2O))[t];
            bool in1 = (ii1 == e), in2 = (ii2 == e);
            if (in1) imp += smf[W1O + t];
            if (in2) imp += smf[W2O + t];
            float kth = (in1 || in2) ? smf[V3O + t] : smf[V2O + t];
            float sd  = smf[LOGI + t * LSTR + NEXP + e];
            float lg  = smf[LOGI + t * LSTR + e];
            float z   = (lg - kth) / (sd + EPS);
            ld += 0.5f * (1.f + erff(z * 0.70710678118654752f));
        }
        smf[IMPO + g * 64 + e] = imp;
        smf[LDO  + g * 64 + e] = ld;
    }
    __syncthreads();

    // ---- fused fixup: warp-per-flagged-token, candidate-only exact dots ----
    const int nflag = ((int*)(smf + NFLG))[0];
    for (int idx = wid; idx < nflag; idx += 16) {
        const int t  = ((int*)(smf + LIST))[idx];
        const int tg = tok0 + t;
        float lga[2], sda[2], nza[2];
#pragma unroll
        for (int j = 0; j < 2; ++j) {
            int e = lane + 32 * j;
            lga[j] = smf[LOGI + t * LSTR + e];
            sda[j] = smf[LOGI + t * LSTR + NEXP + e];
            nza[j] = fmaf(noise[(size_t)tg * NEXP + e], sda[j], lga[j]);
        }
        // approx 3rd max via 3 argmax-exclude passes
        float c0 = nza[0], c1 = nza[1];
        float v3a = -CUDART_INF_F;
#pragma unroll
        for (int pass = 0; pass < 3; ++pass) {
            float m  = fmaxf(c0, c1);
            int  mid = (c0 >= c1) ? (lane * 2) : (lane * 2 + 1);
#pragma unroll
            for (int o = 16; o > 0; o >>= 1) {
                float mv = __shfl_xor_sync(0xFFFFFFFFu, m, o);
                int   mi = __shfl_xor_sync(0xFFFFFFFFu, mid, o);
                if (mv > m || (mv == m && mi < mid)) { m = mv; mid = mi; }
            }
            v3a = m;
            if (mid == lane * 2)     c0 = -CUDART_INF_F;
            if (mid == lane * 2 + 1) c1 = -CUDART_INF_F;
        }
        const float thr = v3a - WINDOW;
        unsigned mask0 = __ballot_sync(0xFFFFFFFFu, nza[0] >= thr);
        unsigned mask1 = __ballot_sync(0xFFFFFFFFu, nza[1] >= thr);

        const float* xr = x + (size_t)tg * DIM;
        float v1x = -CUDART_INF_F, v2x = -CUDART_INF_F, v3x = -CUDART_INF_F;
        int i1 = 0, i2 = 0;

#pragma unroll 1
        for (int half = 0; half < 2; ++half) {
            unsigned m = half ? mask1 : mask0;
            while (m) {
                int e = __ffs(m) - 1 + half * 32;
                m &= m - 1;
                const float* wg = Wg + (size_t)e * DIM;
                const float* wnp = Wn + (size_t)e * DIM;
                float sg = 0.f, sn = 0.f;
#pragma unroll
                for (int jj = 0; jj < 16; ++jj) {
                    int k = lane * 4 + jj * 128;
                    float4 xv = *(const float4*)(xr + k);
                    float4 g4 = *(const float4*)(wg + k);
                    float4 n4 = *(const float4*)(wnp + k);
                    sg = fmaf(xv.x, g4.x, fmaf(xv.y, g4.y, fmaf(xv.z, g4.z, fmaf(xv.w, g4.w, sg))));
                    sn = fmaf(xv.x, n4.x, fmaf(xv.y, n4.y, fmaf(xv.z, n4.z, fmaf(xv.w, n4.w, sn))));
                }
#pragma unroll
                for (int o = 16; o > 0; o >>= 1) {
                    sg += __shfl_xor_sync(0xFFFFFFFFu, sg, o);
                    sn += __shfl_xor_sync(0xFFFFFFFFu, sn, o);
                }
                float sp  = fmaxf(sn, 0.f) + log1pf(expf(-fabsf(sn)));
                float sdx = sp + EPS;
                float nzx = fmaf(noise[(size_t)tg * NEXP + e], sdx, sg);
                if (nzx > v1x)      { v3x = v2x; v2x = v1x; i2 = i1; v1x = nzx; i1 = e; }
                else if (nzx > v2x) { v3x = v2x; v2x = nzx; i2 = e; }
                else if (nzx > v3x) { v3x = nzx; }
            }
        }

        float ed  = expf(v2x - v1x);
        float inv = 1.f / (1.f + ed);
        float w1 = inv, w2 = ed * inv;
        if (lane == 0) {
            out[2 * tg]                    = (float)i1;
            out[2 * tg + 1]                = (float)i2;
            out[2 * N_TOKENS + 2 * tg]     = w1;
            out[2 * N_TOKENS + 2 * tg + 1] = w2;
            out[4 * N_TOKENS + tg]         = w1;
            smf[FIMP + wid * 64 + i1] += w1;
            smf[FIMP + wid * 64 + i2] += w2;
        }
#pragma unroll
        for (int j = 0; j < 2; ++j) {
            int e = lane + 32 * j;
            float kth = (e == i1 || e == i2) ? v3x : v2x;
            float z = (lga[j] - kth) / (sda[j] + EPS);
            smf[FLD2 + wid * 64 + e] += 0.5f * (1.f + erff(z * 0.70710678118654752f));
        }
    }
    __syncthreads();

    // per-block partial store (approx + fixup)
    if (tid < NEXP) {
        float si = 0.f, sl = 0.f;
#pragma unroll
        for (int g = 0; g < 8; ++g) { si += smf[IMPO + g * 64 + tid]; sl += smf[LDO + g * 64 + tid]; }
#pragma unroll
        for (int q = 0; q < 16; ++q) { si += smf[FIMP + q * 64 + tid]; sl += smf[FLD2 + q * 64 + tid]; }
        g_imp_part [b * NEXP + tid] = si;
        g_load_part[b * NEXP + tid] = sl;
    }

    // ---- fused finalize: last block computes aux ----
    __threadfence();
    __shared__ int lastflag;
    if (tid == 0) {
        unsigned tk = atomicAdd(&g_ticket, 1u);
        lastflag = (tk == (unsigned)(NBLK - 1));
    }
    __syncthreads();
    if (!lastflag) return;

    __shared__ float fimp[8][64], fld[8][64];
    {
        const int e = tid & 63, g = tid >> 6;   // 8 groups
        float si = 0.f, sl = 0.f;
        for (int q = g; q < NBLK; q += 8) {
            si += g_imp_part [q * NEXP + e];
            sl += g_load_part[q * NEXP + e];
        }
        fimp[g][e] = si; fld[g][e] = sl;
    }
    __syncthreads();
    __shared__ float timp[64], tld[64];
    if (tid < 64) {
        float a = 0.f, c = 0.f;
#pragma unroll
        for (int q = 0; q < 8; ++q) { a += fimp[q][tid]; c += fld[q][tid]; }
        timp[tid] = a; tld[tid] = c;
    }
    __syncthreads();
    if (tid < 32) {
        float si = timp[tid] + timp[tid + 32];
        float sl = tld[tid]  + tld[tid + 32];
#pragma unroll
        for (int o = 16; o > 0; o >>= 1) {
            si += __shfl_xor_sync(0xFFFFFFFFu, si, o);
            sl += __shfl_xor_sync(0xFFFFFFFFu, sl, o);
        }
        float mi = si * (1.f / NEXP), ml = sl * (1.f / NEXP);
        float d0 = timp[tid] - mi, d1 = timp[tid + 32] - mi;
        float e0 = tld[tid]  - ml, e1 = tld[tid + 32]  - ml;
        float vi = d0 * d0 + d1 * d1;
        float vl = e0 * e0 + e1 * e1;
#pragma unroll
        for (int o = 16; o > 0; o >>= 1) {
            vi += __shfl_xor_sync(0xFFFFFFFFu, vi, o);
            vl += __shfl_xor_sync(0xFFFFFFFFu, vl, o);
        }
        vi *= (1.f / NEXP); vl *= (1.f / NEXP);
        if (tid == 0)
            out[5 * N_TOKENS] = 0.1f * (vi / (mi * mi + EPS)) + 0.1f * (vl / (ml * ml + EPS));
    }
}

extern "C" void kernel_launch(void* const* d_in, const int* in_sizes, int n_in,
                              void* d_out, int out_size)
{
    const float* x     = (const float*)d_in[0];
    const float* noise = (const float*)d_in[1];
    const float* Wg    = (const float*)d_in[2];
    const float* Wn    = (const float*)d_in[3];
    float* out = (float*)d_out;

    cudaFuncSetAttribute(router_main_kernel,
                         cudaFuncAttributeMaxDynamicSharedMemorySize, SMEM_BYTES);
    wpack_kernel<<<128, 256>>>(Wg, Wn);
    router_main_kernel<<<NBLK, NTHREADS, SMEM_BYTES>>>(x, noise, Wg, Wn, out);
}